// round 1
// baseline (speedup 1.0000x reference)
#include <cuda_runtime.h>
#include <math.h>

// Energy-distance loss, fused:
//   a1 = 2/(n*m*d) * sum_{i,j} |lat_i - z_j|
//   b1 = 1/(n*n*d) * sum_{i,j} |lat_i - lat_j|   (= 2*upper/(n^2 d))
//   c1 = 1/(m*m*d) * sum_{i,j} |z_i - z_j|       (= 2*upper/(m^2 d))
//   out = a1 - b1 - c1
// Distances via |a|^2 + |b|^2 - 2 a.b with precomputed row norms, fp32 FMA
// (packed fma.rn.f32x2 for 2x FFMA throughput on sm_103a), IEEE sqrtf,
// deterministic double reduction of per-block partials.

#define DD   64
#define TILE 128
#define NT   256
#define MAXN 16384
#define MAXM 4096
#define MAXPART 16384

typedef unsigned long long ull;

__device__ float  g_normA[MAXN];
__device__ float  g_normB[MAXM];
__device__ double g_part[MAXPART];

__device__ __forceinline__ ull pack2(float x, float y) {
    ull r; asm("mov.b64 %0, {%1, %2};" : "=l"(r) : "f"(x), "f"(y)); return r;
}
__device__ __forceinline__ void unpack2(ull v, float& x, float& y) {
    asm("mov.b64 {%0, %1}, %2;" : "=f"(x), "=f"(y) : "l"(v));
}
__device__ __forceinline__ void fma2(ull& d, ull a, ull b) {
    // packed fp32x2 FMA: d.lo += a.lo*b.lo ; d.hi += a.hi*b.hi (IEEE rn, same as scalar FFMA)
    asm("fma.rn.f32x2 %0, %1, %2, %0;" : "+l"(d) : "l"(a), "l"(b));
}

__global__ void norm_kernel(const float* __restrict__ X, int n, int which) {
    int i = blockIdx.x * blockDim.x + threadIdx.x;
    if (i >= n) return;
    const float4* r = (const float4*)(X + (size_t)i * DD);
    float s = 0.f;
#pragma unroll
    for (int q = 0; q < DD / 4; q++) {
        float4 v = r[q];
        s += v.x * v.x + v.y * v.y + v.z * v.z + v.w * v.w;
    }
    (which ? g_normB : g_normA)[i] = s;
}

__global__ void __launch_bounds__(NT, 2) pairsum_kernel(
    const float* __restrict__ A, const float* __restrict__ B,
    int selA, int selB, int sym, int partBase)
{
    extern __shared__ float smem[];
    float* sA  = smem;                    // [DD][TILE] k-major
    float* sB  = smem + DD * TILE;        // [DD][TILE]
    float* sNa = smem + 2 * DD * TILE;    // [TILE]
    float* sNb = sNa + TILE;              // [TILE]

    int bi, bj;
    if (sym) {
        // map linear block id -> upper-triangle tile (bi <= bj)
        int t = (int)blockIdx.x;
        int b = (int)((sqrtf(8.f * (float)t + 1.f) - 1.f) * 0.5f);
        while ((b + 1) * (b + 2) / 2 <= t) ++b;
        while (b * (b + 1) / 2 > t) --b;
        bj = b; bi = t - b * (b + 1) / 2;
    } else {
        bj = (int)blockIdx.x; bi = (int)blockIdx.y;
    }

    const float* nAp = selA ? g_normB : g_normA;
    const float* nBp = selB ? g_normB : g_normA;

    int row0 = bi * TILE, col0 = bj * TILE;
    int tid = (int)threadIdx.x;

    // load both tiles, transposed into k-major shared layout
    for (int idx = tid; idx < TILE * (DD / 4); idx += NT) {
        int r = idx >> 4, q = idx & 15;
        float4 v = *(const float4*)(A + (size_t)(row0 + r) * DD + q * 4);
        sA[(q * 4 + 0) * TILE + r] = v.x;
        sA[(q * 4 + 1) * TILE + r] = v.y;
        sA[(q * 4 + 2) * TILE + r] = v.z;
        sA[(q * 4 + 3) * TILE + r] = v.w;
        float4 w = *(const float4*)(B + (size_t)(col0 + r) * DD + q * 4);
        sB[(q * 4 + 0) * TILE + r] = w.x;
        sB[(q * 4 + 1) * TILE + r] = w.y;
        sB[(q * 4 + 2) * TILE + r] = w.z;
        sB[(q * 4 + 3) * TILE + r] = w.w;
    }
    if (tid < TILE) { sNa[tid] = nAp[row0 + tid]; sNb[tid] = nBp[col0 + tid]; }
    __syncthreads();

    int ib = (tid >> 4) * 8;   // 8 A-rows per thread
    int jb = (tid & 15) * 8;   // 8 B-rows per thread (as 4 f32x2 pairs)

    ull acc[8][4];
#pragma unroll
    for (int i = 0; i < 8; i++)
#pragma unroll
        for (int j = 0; j < 4; j++) acc[i][j] = 0ull;

#pragma unroll 4
    for (int k = 0; k < DD; k++) {
        const float4 a03 = *(const float4*)(sA + k * TILE + ib);
        const float4 a47 = *(const float4*)(sA + k * TILE + ib + 4);
        const float4 b03 = *(const float4*)(sB + k * TILE + jb);
        const float4 b47 = *(const float4*)(sB + k * TILE + jb + 4);
        ull bp0 = pack2(b03.x, b03.y), bp1 = pack2(b03.z, b03.w);
        ull bp2 = pack2(b47.x, b47.y), bp3 = pack2(b47.z, b47.w);
        float av[8] = {a03.x, a03.y, a03.z, a03.w, a47.x, a47.y, a47.z, a47.w};
#pragma unroll
        for (int ii = 0; ii < 8; ii++) {
            ull ad = pack2(av[ii], av[ii]);
            fma2(acc[ii][0], ad, bp0);
            fma2(acc[ii][1], ad, bp1);
            fma2(acc[ii][2], ad, bp2);
            fma2(acc[ii][3], ad, bp3);
        }
    }

    // epilogue: sq = |a|^2 + |b|^2 - 2 dot, clamp, sqrt, (triangle mask), sum
    float tsum = 0.f;
#pragma unroll
    for (int ii = 0; ii < 8; ii++) {
        int gi = row0 + ib + ii;
        float nai = sNa[ib + ii];
#pragma unroll
        for (int jp = 0; jp < 4; jp++) {
            float d0, d1; unpack2(acc[ii][jp], d0, d1);
            int j0 = jb + jp * 2;
            float s0 = fmaxf(nai + sNb[j0]     - 2.f * d0, 0.f);
            float s1 = fmaxf(nai + sNb[j0 + 1] - 2.f * d1, 0.f);
            float r0 = sqrtf(s0), r1 = sqrtf(s1);
            if (sym) {
                if (gi >= col0 + j0)     r0 = 0.f;  // keep strict upper triangle only
                if (gi >= col0 + j0 + 1) r1 = 0.f;
            }
            tsum += r0 + r1;
        }
    }

    // block reduction: warp shuffle, then 8 partials in (reused) shared
#pragma unroll
    for (int off = 16; off > 0; off >>= 1)
        tsum += __shfl_down_sync(0xffffffffu, tsum, off);
    __syncthreads();
    if ((tid & 31) == 0) smem[tid >> 5] = tsum;
    __syncthreads();
    if (tid == 0) {
        float bs = 0.f;
#pragma unroll
        for (int w = 0; w < NT / 32; w++) bs += smem[w];
        int lin = sym ? (int)blockIdx.x
                      : (int)(blockIdx.y * gridDim.x + blockIdx.x);
        g_part[partBase + lin] = (double)bs;  // one writer per slot: deterministic
    }
}

__global__ void finalize_kernel(float* out, int cX, int cLL, int cZZ,
                                double sX, double sLL, double sZZ)
{
    __shared__ double red[NT];
    int tid = (int)threadIdx.x;
    double a = 0.0, b = 0.0, c = 0.0;
    for (int i = tid; i < cX;  i += NT) a += g_part[i];
    for (int i = tid; i < cLL; i += NT) b += g_part[cX + i];
    for (int i = tid; i < cZZ; i += NT) c += g_part[cX + cLL + i];

    red[tid] = a; __syncthreads();
    for (int s = NT / 2; s > 0; s >>= 1) { if (tid < s) red[tid] += red[tid + s]; __syncthreads(); }
    double SX = red[0]; __syncthreads();

    red[tid] = b; __syncthreads();
    for (int s = NT / 2; s > 0; s >>= 1) { if (tid < s) red[tid] += red[tid + s]; __syncthreads(); }
    double SLL = red[0]; __syncthreads();

    red[tid] = c; __syncthreads();
    for (int s = NT / 2; s > 0; s >>= 1) { if (tid < s) red[tid] += red[tid + s]; __syncthreads(); }
    double SZZ = red[0];

    if (tid == 0)
        out[0] = (float)(SX * sX - SLL * sLL - SZZ * sZZ);
}

extern "C" void kernel_launch(void* const* d_in, const int* in_sizes, int n_in,
                              void* d_out, int out_size)
{
    const float* latent = (const float*)d_in[0];
    const float* z      = (const float*)d_in[1];
    float* out = (float*)d_out;

    int n = in_sizes[0] / DD;   // 16384
    int m = in_sizes[1] / DD;   // 4096
    int tN = n / TILE;          // 128
    int tM = m / TILE;          // 32
    int cX  = tN * tM;              // cross tiles
    int cLL = tN * (tN + 1) / 2;    // latent-latent triangle tiles
    int cZZ = tM * (tM + 1) / 2;    // z-z triangle tiles

    size_t smem = (size_t)(2 * DD * TILE + 2 * TILE) * sizeof(float);  // 66560 B
    cudaFuncSetAttribute(pairsum_kernel,
                         cudaFuncAttributeMaxDynamicSharedMemorySize, (int)smem);

    norm_kernel<<<(n + 255) / 256, 256>>>(latent, n, 0);
    norm_kernel<<<(m + 255) / 256, 256>>>(z, m, 1);

    // cross: latent x z, full grid, partials [0, cX)
    pairsum_kernel<<<dim3(tM, tN), NT, smem>>>(latent, z, 0, 1, 0, 0);
    // latent x latent, upper-triangle tiles, partials [cX, cX+cLL)
    pairsum_kernel<<<cLL, NT, smem>>>(latent, latent, 0, 0, 1, cX);
    // z x z, upper-triangle tiles, partials [cX+cLL, cX+cLL+cZZ)
    pairsum_kernel<<<cZZ, NT, smem>>>(z, z, 1, 1, 1, cX + cLL);

    finalize_kernel<<<1, NT>>>(out, cX, cLL, cZZ,
                               2.0 / ((double)n * (double)m * DD),
                               2.0 / ((double)n * (double)n * DD),
                               2.0 / ((double)m * (double)m * DD));
}

// round 4
// speedup vs baseline: 1.1938x; 1.1938x over previous
#include <cuda_runtime.h>
#include <math.h>

// Energy-distance loss, fused GEMM-style:
//   dist^2 = |a|^2 + |b|^2 - 2 a.b  (fp32 FMA, packed fma.rn.f32x2)
//   out = a1 - b1 - c1 with symmetric sums done on triangle tiles only.
// R2-R4: 16x8 microtile (fma-bound, not smem-bound), conflict-free SMEM.

#define DD   64
#define TILE 128
#define NT   128
#define MAXN 16384
#define MAXM 4096
#define MAXPART 16384

typedef unsigned long long ull;

__device__ float  g_normA[MAXN];
__device__ float  g_normB[MAXM];
__device__ double g_part[MAXPART];

__device__ __forceinline__ ull pack2(float x, float y) {
    ull r; asm("mov.b64 %0, {%1, %2};" : "=l"(r) : "f"(x), "f"(y)); return r;
}
__device__ __forceinline__ void unpack2(ull v, float& x, float& y) {
    asm("mov.b64 {%0, %1}, %2;" : "=f"(x), "=f"(y) : "l"(v));
}
__device__ __forceinline__ void fma2(ull& d, ull a, ull b) {
    // packed fp32x2 FMA (IEEE rn per lane, identical rounding to scalar FFMA)
    asm("fma.rn.f32x2 %0, %1, %2, %0;" : "+l"(d) : "l"(a), "l"(b));
}
// 16B shared load directly into an aligned u64 pair: (f0,f1),(f2,f3) packed free.
__device__ __forceinline__ void lds_v2u64(ull& x, ull& y, const float* p) {
    unsigned a = (unsigned)__cvta_generic_to_shared(p);
    asm volatile("ld.shared.v2.u64 {%0, %1}, [%2];" : "=l"(x), "=l"(y) : "r"(a));
}

__global__ void norm_kernel(const float* __restrict__ X, int n, int which) {
    int i = blockIdx.x * blockDim.x + threadIdx.x;
    if (i >= n) return;
    const float4* r = (const float4*)(X + (size_t)i * DD);
    float s = 0.f;
#pragma unroll
    for (int q = 0; q < DD / 4; q++) {
        float4 v = r[q];
        s += v.x * v.x + v.y * v.y + v.z * v.z + v.w * v.w;
    }
    (which ? g_normB : g_normA)[i] = s;
}

__global__ void __launch_bounds__(NT, 2) pairsum_kernel(
    const float* __restrict__ A, const float* __restrict__ B,
    int selA, int selB, int sym, int partBase)
{
    extern __shared__ float smem[];
    float* sA  = smem;                    // [DD][TILE] k-major
    float* sB  = smem + DD * TILE;        // [DD][TILE]
    float* sNa = smem + 2 * DD * TILE;    // [TILE]
    float* sNb = sNa + TILE;              // [TILE]

    int bi, bj;
    if (sym) {
        int t = (int)blockIdx.x;
        int b = (int)((sqrtf(8.f * (float)t + 1.f) - 1.f) * 0.5f);
        while ((b + 1) * (b + 2) / 2 <= t) ++b;
        while (b * (b + 1) / 2 > t) --b;
        bj = b; bi = t - b * (b + 1) / 2;     // bi <= bj
    } else {
        bj = (int)blockIdx.x; bi = (int)blockIdx.y;
    }

    const float* nAp = selA ? g_normB : g_normA;
    const float* nBp = selB ? g_normB : g_normA;

    int row0 = bi * TILE, col0 = bj * TILE;
    int tid = (int)threadIdx.x;

    // Tile load, transposed to k-major. Mapping idx=(q,r) with r=idx&127 makes
    // STS bank = r%32 distinct across the warp -> conflict-free stores.
    for (int idx = tid; idx < TILE * (DD / 4); idx += NT) {
        int r = idx & (TILE - 1);
        int q = idx >> 7;                 // 0..15, 16B column chunk
        float4 v = *(const float4*)(A + (size_t)(row0 + r) * DD + q * 4);
        sA[(q * 4 + 0) * TILE + r] = v.x;
        sA[(q * 4 + 1) * TILE + r] = v.y;
        sA[(q * 4 + 2) * TILE + r] = v.z;
        sA[(q * 4 + 3) * TILE + r] = v.w;
        float4 w = *(const float4*)(B + (size_t)(col0 + r) * DD + q * 4);
        sB[(q * 4 + 0) * TILE + r] = w.x;
        sB[(q * 4 + 1) * TILE + r] = w.y;
        sB[(q * 4 + 2) * TILE + r] = w.z;
        sB[(q * 4 + 3) * TILE + r] = w.w;
    }
    if (tid < TILE) { sNa[tid] = nAp[row0 + tid]; sNb[tid] = nBp[col0 + tid]; }
    __syncthreads();

    // 16x8 microtile. A rows (i): 4 chunks of 4 at c, c+32, c+64, c+96 where
    // c=(tid&7)*4 -> each LDS phase (8 lanes) covers one contiguous 128B span:
    // conflict-free. B cols (j): j0..j0+7, j0=(tid>>3)*8 -> phase-broadcast.
    int c  = (tid & 7) * 4;
    int j0 = (tid >> 3) * 8;

    ull acc[8][8];                         // [i-pair][j], pair = (i, i+1)
#pragma unroll
    for (int p = 0; p < 8; p++)
#pragma unroll
        for (int j = 0; j < 8; j++) acc[p][j] = 0ull;

#pragma unroll 4
    for (int k = 0; k < DD; k++) {
        const float* rowA = sA + k * TILE;
        const float* rowB = sB + k * TILE;
        ull a[8];                          // 8 i-pairs, packed for free
        lds_v2u64(a[0], a[1], rowA + c);
        lds_v2u64(a[2], a[3], rowA + c + 32);
        lds_v2u64(a[4], a[5], rowA + c + 64);
        lds_v2u64(a[6], a[7], rowA + c + 96);
        const float4 b03 = *(const float4*)(rowB + j0);
        const float4 b47 = *(const float4*)(rowB + j0 + 4);
        ull bd[8];
        bd[0] = pack2(b03.x, b03.x); bd[1] = pack2(b03.y, b03.y);
        bd[2] = pack2(b03.z, b03.z); bd[3] = pack2(b03.w, b03.w);
        bd[4] = pack2(b47.x, b47.x); bd[5] = pack2(b47.y, b47.y);
        bd[6] = pack2(b47.z, b47.z); bd[7] = pack2(b47.w, b47.w);
#pragma unroll
        for (int p = 0; p < 8; p++) {
#pragma unroll
            for (int j = 0; j < 8; j++) fma2(acc[p][j], a[p], bd[j]);
        }
    }

    // epilogue: sq = |a|^2 + |b|^2 - 2 dot, clamp, sqrt, triangle mask, sum
    float tsum = 0.f;
#pragma unroll
    for (int p = 0; p < 8; p++) {
        int il  = c + (p >> 1) * 32 + (p & 1) * 2;   // local i of pair lane 0
        int gi0 = row0 + il;
        float na0 = sNa[il], na1 = sNa[il + 1];
#pragma unroll
        for (int j = 0; j < 8; j++) {
            float d0, d1; unpack2(acc[p][j], d0, d1);
            float nb = sNb[j0 + j];
            float s0 = fmaxf(na0 + nb - 2.f * d0, 0.f);
            float s1 = fmaxf(na1 + nb - 2.f * d1, 0.f);
            float r0 = sqrtf(s0), r1 = sqrtf(s1);
            if (sym) {
                int gj = col0 + j0 + j;
                if (gi0 >= gj)     r0 = 0.f;   // strict upper triangle only
                if (gi0 + 1 >= gj) r1 = 0.f;
            }
            tsum += r0 + r1;
        }
    }

#pragma unroll
    for (int off = 16; off > 0; off >>= 1)
        tsum += __shfl_down_sync(0xffffffffu, tsum, off);
    __syncthreads();
    if ((tid & 31) == 0) smem[tid >> 5] = tsum;
    __syncthreads();
    if (tid == 0) {
        float bs = 0.f;
#pragma unroll
        for (int w = 0; w < NT / 32; w++) bs += smem[w];
        int lin = sym ? (int)blockIdx.x
                      : (int)(blockIdx.y * gridDim.x + blockIdx.x);
        g_part[partBase + lin] = (double)bs;   // one writer/slot: deterministic
    }
}

#define FNT 256
__global__ void finalize_kernel(float* out, int cX, int cLL, int cZZ,
                                double sX, double sLL, double sZZ)
{
    __shared__ double red[FNT];
    int tid = (int)threadIdx.x;
    double a = 0.0, b = 0.0, c = 0.0;
    for (int i = tid; i < cX;  i += FNT) a += g_part[i];
    for (int i = tid; i < cLL; i += FNT) b += g_part[cX + i];
    for (int i = tid; i < cZZ; i += FNT) c += g_part[cX + cLL + i];

    red[tid] = a; __syncthreads();
    for (int s = FNT / 2; s > 0; s >>= 1) { if (tid < s) red[tid] += red[tid + s]; __syncthreads(); }
    double SX = red[0]; __syncthreads();

    red[tid] = b; __syncthreads();
    for (int s = FNT / 2; s > 0; s >>= 1) { if (tid < s) red[tid] += red[tid + s]; __syncthreads(); }
    double SLL = red[0]; __syncthreads();

    red[tid] = c; __syncthreads();
    for (int s = FNT / 2; s > 0; s >>= 1) { if (tid < s) red[tid] += red[tid + s]; __syncthreads(); }
    double SZZ = red[0];

    if (tid == 0)
        out[0] = (float)(SX * sX - SLL * sLL - SZZ * sZZ);
}

extern "C" void kernel_launch(void* const* d_in, const int* in_sizes, int n_in,
                              void* d_out, int out_size)
{
    const float* latent = (const float*)d_in[0];
    const float* z      = (const float*)d_in[1];
    float* out = (float*)d_out;

    int n = in_sizes[0] / DD;   // 16384
    int m = in_sizes[1] / DD;   // 4096
    int tN = n / TILE;          // 128
    int tM = m / TILE;          // 32
    int cX  = tN * tM;              // 4096 cross tiles
    int cLL = tN * (tN + 1) / 2;    // 8256 latent-latent triangle tiles
    int cZZ = tM * (tM + 1) / 2;    // 528 z-z triangle tiles

    size_t smem = (size_t)(2 * DD * TILE + 2 * TILE) * sizeof(float);  // 66560 B
    cudaFuncSetAttribute(pairsum_kernel,
                         cudaFuncAttributeMaxDynamicSharedMemorySize, (int)smem);

    norm_kernel<<<(n + 255) / 256, 256>>>(latent, n, 0);
    norm_kernel<<<(m + 255) / 256, 256>>>(z, m, 1);

    pairsum_kernel<<<dim3(tM, tN), NT, smem>>>(latent, z, 0, 1, 0, 0);
    pairsum_kernel<<<cLL, NT, smem>>>(latent, latent, 0, 0, 1, cX);
    pairsum_kernel<<<cZZ, NT, smem>>>(z, z, 1, 1, 1, cX + cLL);

    finalize_kernel<<<1, FNT>>>(out, cX, cLL, cZZ,
                                2.0 / ((double)n * (double)m * DD),
                                2.0 / ((double)n * (double)n * DD),
                                2.0 / ((double)m * (double)m * DD));
}